// round 1
// baseline (speedup 1.0000x reference)
#include <cuda_runtime.h>
#include <math.h>

#define Bsz 64
#define TT 512
#define DD 512
#define HH 512
#define G4 2048   // 4*H
#define NCTA 128

// Scratch (static device globals are the sanctioned scratch mechanism)
__device__ float g_xz[2][TT][G4][Bsz];      // [dir][t][gatecol][b]  (512 MB)
__device__ float g_hbuf[2][2][HH][Bsz];     // [buf][dir][hidx][b]
__device__ unsigned g_cnt;                  // barrier arrivals
__device__ volatile unsigned g_phase;       // barrier phase (reset at kernel end)

// ---------------------------------------------------------------------------
// Kernel 1: input projection  xz[dir][t][col][b] = bias[col] + sum_k x[b][t][k]*Wk[k][col]
// Grid: (32 colTiles, 512 t). CTA tile: 128 cols x 64 batch, K=512.
// ---------------------------------------------------------------------------
__global__ __launch_bounds__(256) void proj_kernel(
    const float* __restrict__ x,
    const float* __restrict__ Wfk, const float* __restrict__ bf,
    const float* __restrict__ Wbk, const float* __restrict__ bb)
{
    __shared__ float x_s[32][64];    // [k][b]
    __shared__ float w_s[32][128];   // [k][col]

    const int tx = threadIdx.x;
    const int colTile = blockIdx.x;          // 0..31
    const int t = blockIdx.y;                // 0..511
    const int dir = colTile >> 4;
    const int col0 = (colTile & 15) * 128;   // col offset within this dir's 4H
    const float* __restrict__ Wk = dir ? Wbk : Wfk;
    const float* __restrict__ bias = dir ? bb : bf;

    const int cg = tx & 15;   // 16 col groups of 8
    const int bg = tx >> 4;   // 16 batch groups of 4
    const int c0 = cg * 8;
    const int b0 = bg * 4;

    float acc[8][4];
    #pragma unroll
    for (int i = 0; i < 8; i++)
        #pragma unroll
        for (int j = 0; j < 4; j++) acc[i][j] = 0.f;

    const int xb = tx >> 2;          // 0..63
    const int xk = (tx & 3) * 8;     // 0,8,16,24
    const float* xp_base = x + ((size_t)xb * TT + t) * DD + xk;

    for (int k0 = 0; k0 < DD; k0 += 32) {
        __syncthreads();
        {
            const float* xp = xp_base + k0;
            float4 v0 = *(const float4*)(xp);
            float4 v1 = *(const float4*)(xp + 4);
            x_s[xk + 0][xb] = v0.x; x_s[xk + 1][xb] = v0.y;
            x_s[xk + 2][xb] = v0.z; x_s[xk + 3][xb] = v0.w;
            x_s[xk + 4][xb] = v1.x; x_s[xk + 5][xb] = v1.y;
            x_s[xk + 6][xb] = v1.z; x_s[xk + 7][xb] = v1.w;
        }
        #pragma unroll
        for (int j = 0; j < 4; j++) {
            int idx = tx + j * 256;       // 0..1023 float4 slots
            int kk = idx >> 5;            // 0..31
            int cc = (idx & 31) * 4;      // 0..124
            *(float4*)&w_s[kk][cc] =
                *(const float4*)(Wk + (size_t)(k0 + kk) * G4 + col0 + cc);
        }
        __syncthreads();
        #pragma unroll 8
        for (int k = 0; k < 32; k++) {
            float4 xa = *(float4*)&x_s[k][b0];
            float4 wA = *(float4*)&w_s[k][c0];
            float4 wB = *(float4*)&w_s[k][c0 + 4];
            float xv[4] = {xa.x, xa.y, xa.z, xa.w};
            float wv[8] = {wA.x, wA.y, wA.z, wA.w, wB.x, wB.y, wB.z, wB.w};
            #pragma unroll
            for (int ci = 0; ci < 8; ci++)
                #pragma unroll
                for (int bi = 0; bi < 4; bi++)
                    acc[ci][bi] = fmaf(wv[ci], xv[bi], acc[ci][bi]);
        }
    }

    #pragma unroll
    for (int ci = 0; ci < 8; ci++) {
        int c = col0 + c0 + ci;
        float bv = bias[c];
        float4 o = make_float4(acc[ci][0] + bv, acc[ci][1] + bv,
                               acc[ci][2] + bv, acc[ci][3] + bv);
        *(float4*)&g_xz[dir][t][c][b0] = o;
    }
}

// ---------------------------------------------------------------------------
// Kernel 2: persistent bidirectional LSTM scan.
// 128 CTAs (64 per direction), 1 per SM, co-resident. CTA owns 8 h-indices
// (= 32 gate columns), Wr slice resident in SMEM, c-state in registers.
// ---------------------------------------------------------------------------
__device__ __forceinline__ float sigf(float v) { return 1.f / (1.f + __expf(-v)); }

__device__ __forceinline__ void grid_barrier(unsigned target) {
    __syncthreads();
    if (threadIdx.x == 0) {
        __threadfence();
        unsigned old = atomicAdd(&g_cnt, 1u);
        if (old == NCTA - 1) {
            g_cnt = 0;
            __threadfence();
            g_phase = target;
        } else {
            while (g_phase < target) { }
        }
        __threadfence();
    }
    __syncthreads();
}

__device__ __forceinline__ void grid_barrier_reset() {
    __syncthreads();
    if (threadIdx.x == 0) {
        __threadfence();
        unsigned old = atomicAdd(&g_cnt, 1u);
        if (old == NCTA - 1) {
            g_cnt = 0;
            __threadfence();
            g_phase = 0;      // restore initial state for next graph replay
        }
    }
}

__global__ __launch_bounds__(256, 1) void scan_kernel(
    const float* __restrict__ Wfr, const float* __restrict__ Wbr,
    float* __restrict__ out)
{
    extern __shared__ float smem[];
    float* Wr_s = smem;                       // [512][32]   64 KB
    float* h_s  = smem + 512 * 32;            // [512][64]  128 KB
    float* zbuf = h_s;                        // alias: [4][64][32]  32 KB
    float* zx_s = smem + 512 * 32 + 512 * 64; // [32][64]     8 KB

    const int tx = threadIdx.x;
    const int cta = blockIdx.x;        // 0..127
    const int dir = cta >> 6;
    const int hbase = (cta & 63) * 8;
    const float* __restrict__ Wr = dir ? Wbr : Wfr;

    // Load resident Wr slice: Wr_s[k][gate*8+j] = Wr[k][gate*512 + hbase + j]
    for (int idx = tx; idx < 512 * 32; idx += 256) {
        int k = idx >> 5, c = idx & 31;
        int gate = c >> 3, j = c & 7;
        Wr_s[idx] = Wr[(size_t)k * G4 + gate * HH + hbase + j];
    }

    // Zero our slice of h buffer 0
    for (int idx = tx; idx < 8 * 64; idx += 256) {
        int hj = idx >> 6, b = idx & 63;
        g_hbuf[0][dir][hbase + hj][b] = 0.f;
    }

    // Per-thread persistent cell state: pairs (hj0, b_p) and (hj1, b_p)
    const int b_p = tx & 63;
    const int hj0 = tx >> 6;        // 0..3
    const int hj1 = hj0 + 4;        // 4..7
    float c_reg0 = 0.f, c_reg1 = 0.f;

    // GEMM-phase mapping: 4 k-slices x (8 batch-groups x 8 col-groups)
    const int ks  = tx >> 6;        // k slice 0..3 (128 k each)
    const int pos = tx & 63;
    const int b0  = (pos >> 3) * 8; // 8 batches
    const int c0  = (pos & 7) * 4;  // 4 cols

    float* out_sent = out + (size_t)Bsz * TT * (2 * HH);

    grid_barrier(1);   // hbuf[0] init visible everywhere

    for (int t = 0; t < TT; t++) {
        const int rb = t & 1, wb = (t + 1) & 1;
        const int tq = dir ? (TT - 1 - t) : t;

        // Stage h[512][64] (contiguous copy)
        {
            const float4* src = (const float4*)&g_hbuf[rb][dir][0][0];
            float4* dst = (float4*)h_s;
            #pragma unroll 4
            for (int idx = tx; idx < 512 * 64 / 4; idx += 256)
                dst[idx] = src[idx];
        }
        // Stage xz tile: zx_s[c][b], c = gate*8+j
        {
            const float* xzb = &g_xz[dir][tq][0][0];
            #pragma unroll
            for (int idx = tx; idx < 32 * 64; idx += 256) {
                int c = idx >> 6, b = idx & 63;
                int gate = c >> 3, j = c & 7;
                zx_s[idx] = xzb[(size_t)(gate * HH + hbase + j) * Bsz + b];
            }
        }
        __syncthreads();

        // z-GEMM: acc[bi][ci] over this thread's k slice
        float acc[8][4];
        #pragma unroll
        for (int i = 0; i < 8; i++)
            #pragma unroll
            for (int j = 0; j < 4; j++) acc[i][j] = 0.f;

        const float* hp = h_s + ks * 128 * 64;
        const float* wp = Wr_s + ks * 128 * 32;
        #pragma unroll 4
        for (int kk = 0; kk < 128; kk++) {
            float4 ha = *(const float4*)(hp + kk * 64 + b0);
            float4 hb = *(const float4*)(hp + kk * 64 + b0 + 4);
            float4 w  = *(const float4*)(wp + kk * 32 + c0);
            float hv[8] = {ha.x, ha.y, ha.z, ha.w, hb.x, hb.y, hb.z, hb.w};
            float wv[4] = {w.x, w.y, w.z, w.w};
            #pragma unroll
            for (int bi = 0; bi < 8; bi++)
                #pragma unroll
                for (int ci = 0; ci < 4; ci++)
                    acc[bi][ci] = fmaf(hv[bi], wv[ci], acc[bi][ci]);
        }
        __syncthreads();   // h_s reads done; safe to overwrite with zbuf

        // Partial sums: zbuf[ks][b][c]
        #pragma unroll
        for (int bi = 0; bi < 8; bi++)
            *(float4*)&zbuf[((ks * 64) + b0 + bi) * 32 + c0] =
                make_float4(acc[bi][0], acc[bi][1], acc[bi][2], acc[bi][3]);
        __syncthreads();

        // Gate phase: each thread finishes 2 (hj, b) pairs
        float z0[4], z1[4];
        #pragma unroll
        for (int gate = 0; gate < 4; gate++) {
            float s0 = zx_s[(gate * 8 + hj0) * 64 + b_p];
            float s1 = zx_s[(gate * 8 + hj1) * 64 + b_p];
            #pragma unroll
            for (int k2 = 0; k2 < 4; k2++) {
                s0 += zbuf[(k2 * 64 + b_p) * 32 + gate * 8 + hj0];
                s1 += zbuf[(k2 * 64 + b_p) * 32 + gate * 8 + hj1];
            }
            z0[gate] = s0; z1[gate] = s1;
        }
        float i0 = sigf(z0[0]), f0 = sigf(z0[1]), g0 = tanhf(z0[2]), o0 = sigf(z0[3]);
        c_reg0 = f0 * c_reg0 + i0 * g0;
        float h0v = o0 * tanhf(c_reg0);
        float i1 = sigf(z1[0]), f1 = sigf(z1[1]), g1 = tanhf(z1[2]), o1 = sigf(z1[3]);
        c_reg1 = f1 * c_reg1 + i1 * g1;
        float h1v = o1 * tanhf(c_reg1);

        // Publish h for next step + write word_emb at position tq
        g_hbuf[wb][dir][hbase + hj0][b_p] = h0v;
        g_hbuf[wb][dir][hbase + hj1][b_p] = h1v;
        size_t wo = ((size_t)b_p * TT + tq) * (2 * HH) + dir * HH + hbase;
        out[wo + hj0] = h0v;
        out[wo + hj1] = h1v;
        if (t == TT - 1) {
            size_t so = (size_t)b_p * (2 * HH) + dir * HH + hbase;
            out_sent[so + hj0] = h0v;
            out_sent[so + hj1] = h1v;
        }

        if (t < TT - 1) grid_barrier((unsigned)(t + 2));
    }
    grid_barrier_reset();
}

// ---------------------------------------------------------------------------
extern "C" void kernel_launch(void* const* d_in, const int* in_sizes, int n_in,
                              void* d_out, int out_size) {
    const float* x   = (const float*)d_in[0];
    const float* Wfk = (const float*)d_in[1];
    const float* Wfr = (const float*)d_in[2];
    const float* bf  = (const float*)d_in[3];
    const float* Wbk = (const float*)d_in[4];
    const float* Wbr = (const float*)d_in[5];
    const float* bb  = (const float*)d_in[6];
    float* out = (float*)d_out;

    size_t smem = (size_t)(512 * 32 + 512 * 64 + 32 * 64) * sizeof(float); // 200 KB
    cudaFuncSetAttribute(scan_kernel,
                         cudaFuncAttributeMaxDynamicSharedMemorySize, (int)smem);

    dim3 pg(32, 512);
    proj_kernel<<<pg, 256>>>(x, Wfk, bf, Wbk, bb);
    scan_kernel<<<NCTA, 256, smem>>>(Wfr, Wbr, out);
}

// round 2
// speedup vs baseline: 1.4127x; 1.4127x over previous
#include <cuda_runtime.h>
#include <math.h>

#define Bsz 64
#define TT 512
#define DD 512
#define HH 512
#define G4 2048   // 4*H
#define NCTA 128

// Scratch (static device globals are the sanctioned scratch mechanism)
__device__ float g_xz[2][TT][G4][Bsz];      // [dir][t][gatecol][b]  (512 MB)
__device__ float g_hbuf[2][2][HH][Bsz];     // [buf][dir][hidx][b]
__device__ unsigned g_cnt;                  // barrier arrivals
__device__ volatile unsigned g_phase;       // barrier phase (reset at kernel end)

// ---------------------------------------------------------------------------
// tf32 helpers
// ---------------------------------------------------------------------------
__device__ __forceinline__ unsigned f2tf(float f) {
    unsigned r;
    asm("cvt.rna.tf32.f32 %0, %1;" : "=r"(r) : "f"(f));
    return r;
}

__device__ __forceinline__ void mma1688(float c[4],
                                        unsigned a0, unsigned a1, unsigned a2, unsigned a3,
                                        unsigned b0, unsigned b1) {
    asm volatile(
        "mma.sync.aligned.m16n8k8.row.col.f32.tf32.tf32.f32 "
        "{%0,%1,%2,%3}, {%4,%5,%6,%7}, {%8,%9}, {%0,%1,%2,%3};\n"
        : "+f"(c[0]), "+f"(c[1]), "+f"(c[2]), "+f"(c[3])
        : "r"(a0), "r"(a1), "r"(a2), "r"(a3), "r"(b0), "r"(b1));
}

// ---------------------------------------------------------------------------
// Kernel 1: input projection via tf32 tensor-core MMA.
// C[m=col][n=b] = sum_k W[k][col] * x[b][t][k], i.e. A = W^T (row-major m x k),
// B = x tile (col-major k x n). Output lands directly in g_xz[dir][t][col][b].
// CTA: 512 threads, tile 256 cols x 64 b x 2 timesteps, K=512 in chunks of 32.
// Grid: (8 colTiles, 256 tPairs, 2 dirs).
// ---------------------------------------------------------------------------
#define W_PITCH 264          // 256 + 8 pad: row stride mod 32 banks == 8
#define X_PITCH 36           // 32 + 4 pad:  row stride mod 32 banks == 4
#define W_ELEMS (32 * W_PITCH)       // 8448
#define X_ELEMS (64 * X_PITCH)       // 2304 per t-set
#define PROJ_SMEM ((W_ELEMS + 2 * X_ELEMS) * 4)   // 52224 bytes

__global__ __launch_bounds__(512, 1) void proj_mma_kernel(
    const float* __restrict__ x,
    const float* __restrict__ Wfk, const float* __restrict__ bf,
    const float* __restrict__ Wbk, const float* __restrict__ bb)
{
    extern __shared__ unsigned psm[];
    unsigned* w_s = psm;                 // [32][W_PITCH]  (k x col)
    unsigned* x_s = psm + W_ELEMS;       // [2][64][X_PITCH] (ts x b x k)

    const int tid = threadIdx.x;
    const int colTile = blockIdx.x;      // 0..7
    const int tpair = blockIdx.y;        // 0..255
    const int dir = blockIdx.z;          // 0..1
    const int colbase = colTile * 256;
    const float* __restrict__ Wk = dir ? Wbk : Wfk;
    const float* __restrict__ bias = dir ? bb : bf;

    const int lane = tid & 31;
    const int grp = lane >> 2;           // 0..7
    const int tig = lane & 3;            // 0..3
    const int wid = tid >> 5;            // 0..15
    const int wn = wid & 1;              // n (batch) half: b base = wn*32
    const int wm = wid >> 1;             // m (col) tile: col base = wm*32

    float acc[2][2][4][4];               // [ts][mt][nt][4]
    #pragma unroll
    for (int a = 0; a < 2; a++)
        #pragma unroll
        for (int b = 0; b < 2; b++)
            #pragma unroll
            for (int c = 0; c < 4; c++)
                #pragma unroll
                for (int d = 0; d < 4; d++) acc[a][b][c][d] = 0.f;

    #pragma unroll 1
    for (int k0 = 0; k0 < DD; k0 += 32) {
        __syncthreads();
        // Stage W chunk: w_s[kk][cc] = tf32(Wk[k0+kk][colbase+cc]); 32x256
        #pragma unroll
        for (int j = 0; j < 4; j++) {
            int e4 = tid + j * 512;            // float4 index 0..2047
            int kk = e4 >> 6;                  // 64 float4 per row
            int cc = (e4 & 63) * 4;
            float4 v = *(const float4*)(Wk + (size_t)(k0 + kk) * G4 + colbase + cc);
            uint4 u = make_uint4(f2tf(v.x), f2tf(v.y), f2tf(v.z), f2tf(v.w));
            *(uint4*)(w_s + kk * W_PITCH + cc) = u;
        }
        // Stage x chunks for both timesteps: x_s[ts][b][kk] (b-major for
        // conflict-free STS.128 and bank-clean B-fragment LDS)
        #pragma unroll
        for (int j = 0; j < 2; j++) {
            int f4 = tid + j * 512;            // 0..1023
            int ts = f4 >> 9;
            int r = f4 & 511;
            int b = r >> 3;
            int kc4 = (r & 7) * 4;
            int t = tpair * 2 + ts;
            float4 v = *(const float4*)(x + ((size_t)b * TT + t) * DD + k0 + kc4);
            uint4 u = make_uint4(f2tf(v.x), f2tf(v.y), f2tf(v.z), f2tf(v.w));
            *(uint4*)(x_s + ts * X_ELEMS + b * X_PITCH + kc4) = u;
        }
        __syncthreads();

        #pragma unroll
        for (int ks = 0; ks < 4; ks++) {
            const int kr = ks * 8;
            // A fragments (W^T): a0=A[grp][tig], a1=A[grp+8][tig],
            //                    a2=A[grp][tig+4], a3=A[grp+8][tig+4]
            unsigned a[2][4];
            #pragma unroll
            for (int mt = 0; mt < 2; mt++) {
                int cb = wm * 32 + mt * 16 + grp;
                a[mt][0] = w_s[(kr + tig) * W_PITCH + cb];
                a[mt][1] = w_s[(kr + tig) * W_PITCH + cb + 8];
                a[mt][2] = w_s[(kr + tig + 4) * W_PITCH + cb];
                a[mt][3] = w_s[(kr + tig + 4) * W_PITCH + cb + 8];
            }
            // B fragments (x): b0=B[tig][grp], b1=B[tig+4][grp]; n index = b
            unsigned bb_[2][4][2];
            #pragma unroll
            for (int ts = 0; ts < 2; ts++)
                #pragma unroll
                for (int nt = 0; nt < 4; nt++) {
                    int idx = ts * X_ELEMS + (wn * 32 + nt * 8 + grp) * X_PITCH + kr + tig;
                    bb_[ts][nt][0] = x_s[idx];
                    bb_[ts][nt][1] = x_s[idx + 4];
                }
            #pragma unroll
            for (int ts = 0; ts < 2; ts++)
                #pragma unroll
                for (int mt = 0; mt < 2; mt++)
                    #pragma unroll
                    for (int nt = 0; nt < 4; nt++)
                        mma1688(acc[ts][mt][nt],
                                a[mt][0], a[mt][1], a[mt][2], a[mt][3],
                                bb_[ts][nt][0], bb_[ts][nt][1]);
        }
    }

    // Epilogue: add bias, store to g_xz[dir][t][col][b].
    // c0: (m=grp,   n=tig*2), c1: (grp,   tig*2+1)
    // c2: (m=grp+8, n=tig*2), c3: (grp+8, tig*2+1)
    #pragma unroll
    for (int ts = 0; ts < 2; ts++) {
        int t = tpair * 2 + ts;
        float* gx = &g_xz[dir][t][0][0];
        #pragma unroll
        for (int mt = 0; mt < 2; mt++) {
            int col = colbase + wm * 32 + mt * 16 + grp;
            float bv = bias[col];
            float bv8 = bias[col + 8];
            #pragma unroll
            for (int nt = 0; nt < 4; nt++) {
                int b = wn * 32 + nt * 8 + tig * 2;
                float2 lo = make_float2(acc[ts][mt][nt][0] + bv,
                                        acc[ts][mt][nt][1] + bv);
                float2 hi = make_float2(acc[ts][mt][nt][2] + bv8,
                                        acc[ts][mt][nt][3] + bv8);
                *(float2*)(gx + (size_t)col * Bsz + b) = lo;
                *(float2*)(gx + (size_t)(col + 8) * Bsz + b) = hi;
            }
        }
    }
}

// ---------------------------------------------------------------------------
// Kernel 2: persistent bidirectional LSTM scan (unchanged from R0).
// ---------------------------------------------------------------------------
__device__ __forceinline__ float sigf(float v) { return 1.f / (1.f + __expf(-v)); }

__device__ __forceinline__ void grid_barrier(unsigned target) {
    __syncthreads();
    if (threadIdx.x == 0) {
        __threadfence();
        unsigned old = atomicAdd(&g_cnt, 1u);
        if (old == NCTA - 1) {
            g_cnt = 0;
            __threadfence();
            g_phase = target;
        } else {
            while (g_phase < target) { }
        }
        __threadfence();
    }
    __syncthreads();
}

__device__ __forceinline__ void grid_barrier_reset() {
    __syncthreads();
    if (threadIdx.x == 0) {
        __threadfence();
        unsigned old = atomicAdd(&g_cnt, 1u);
        if (old == NCTA - 1) {
            g_cnt = 0;
            __threadfence();
            g_phase = 0;      // restore initial state for next graph replay
        }
    }
}

__global__ __launch_bounds__(256, 1) void scan_kernel(
    const float* __restrict__ Wfr, const float* __restrict__ Wbr,
    float* __restrict__ out)
{
    extern __shared__ float smem[];
    float* Wr_s = smem;                       // [512][32]   64 KB
    float* h_s  = smem + 512 * 32;            // [512][64]  128 KB
    float* zbuf = h_s;                        // alias: [4][64][32]  32 KB
    float* zx_s = smem + 512 * 32 + 512 * 64; // [32][64]     8 KB

    const int tx = threadIdx.x;
    const int cta = blockIdx.x;        // 0..127
    const int dir = cta >> 6;
    const int hbase = (cta & 63) * 8;
    const float* __restrict__ Wr = dir ? Wbr : Wfr;

    // Load resident Wr slice: Wr_s[k][gate*8+j] = Wr[k][gate*512 + hbase + j]
    for (int idx = tx; idx < 512 * 32; idx += 256) {
        int k = idx >> 5, c = idx & 31;
        int gate = c >> 3, j = c & 7;
        Wr_s[idx] = Wr[(size_t)k * G4 + gate * HH + hbase + j];
    }

    // Zero our slice of h buffer 0
    for (int idx = tx; idx < 8 * 64; idx += 256) {
        int hj = idx >> 6, b = idx & 63;
        g_hbuf[0][dir][hbase + hj][b] = 0.f;
    }

    // Per-thread persistent cell state: pairs (hj0, b_p) and (hj1, b_p)
    const int b_p = tx & 63;
    const int hj0 = tx >> 6;        // 0..3
    const int hj1 = hj0 + 4;        // 4..7
    float c_reg0 = 0.f, c_reg1 = 0.f;

    // GEMM-phase mapping: 4 k-slices x (8 batch-groups x 8 col-groups)
    const int ks  = tx >> 6;        // k slice 0..3 (128 k each)
    const int pos = tx & 63;
    const int b0  = (pos >> 3) * 8; // 8 batches
    const int c0  = (pos & 7) * 4;  // 4 cols

    float* out_sent = out + (size_t)Bsz * TT * (2 * HH);

    grid_barrier(1);   // hbuf[0] init visible everywhere

    for (int t = 0; t < TT; t++) {
        const int rb = t & 1, wb = (t + 1) & 1;
        const int tq = dir ? (TT - 1 - t) : t;

        // Stage h[512][64] (contiguous copy)
        {
            const float4* src = (const float4*)&g_hbuf[rb][dir][0][0];
            float4* dst = (float4*)h_s;
            #pragma unroll 4
            for (int idx = tx; idx < 512 * 64 / 4; idx += 256)
                dst[idx] = src[idx];
        }
        // Stage xz tile: zx_s[c][b], c = gate*8+j
        {
            const float* xzb = &g_xz[dir][tq][0][0];
            #pragma unroll
            for (int idx = tx; idx < 32 * 64; idx += 256) {
                int c = idx >> 6, b = idx & 63;
                int gate = c >> 3, j = c & 7;
                zx_s[idx] = xzb[(size_t)(gate * HH + hbase + j) * Bsz + b];
            }
        }
        __syncthreads();

        // z-GEMM: acc[bi][ci] over this thread's k slice
        float acc[8][4];
        #pragma unroll
        for (int i = 0; i < 8; i++)
            #pragma unroll
            for (int j = 0; j < 4; j++) acc[i][j] = 0.f;

        const float* hp = h_s + ks * 128 * 64;
        const float* wp = Wr_s + ks * 128 * 32;
        #pragma unroll 4
        for (int kk = 0; kk < 128; kk++) {
            float4 ha = *(const float4*)(hp + kk * 64 + b0);
            float4 hb = *(const float4*)(hp + kk * 64 + b0 + 4);
            float4 w  = *(const float4*)(wp + kk * 32 + c0);
            float hv[8] = {ha.x, ha.y, ha.z, ha.w, hb.x, hb.y, hb.z, hb.w};
            float wv[4] = {w.x, w.y, w.z, w.w};
            #pragma unroll
            for (int bi = 0; bi < 8; bi++)
                #pragma unroll
                for (int ci = 0; ci < 4; ci++)
                    acc[bi][ci] = fmaf(hv[bi], wv[ci], acc[bi][ci]);
        }
        __syncthreads();   // h_s reads done; safe to overwrite with zbuf

        // Partial sums: zbuf[ks][b][c]
        #pragma unroll
        for (int bi = 0; bi < 8; bi++)
            *(float4*)&zbuf[((ks * 64) + b0 + bi) * 32 + c0] =
                make_float4(acc[bi][0], acc[bi][1], acc[bi][2], acc[bi][3]);
        __syncthreads();

        // Gate phase: each thread finishes 2 (hj, b) pairs
        float z0[4], z1[4];
        #pragma unroll
        for (int gate = 0; gate < 4; gate++) {
            float s0 = zx_s[(gate * 8 + hj0) * 64 + b_p];
            float s1 = zx_s[(gate * 8 + hj1) * 64 + b_p];
            #pragma unroll
            for (int k2 = 0; k2 < 4; k2++) {
                s0 += zbuf[(k2 * 64 + b_p) * 32 + gate * 8 + hj0];
                s1 += zbuf[(k2 * 64 + b_p) * 32 + gate * 8 + hj1];
            }
            z0[gate] = s0; z1[gate] = s1;
        }
        float i0 = sigf(z0[0]), f0 = sigf(z0[1]), g0 = tanhf(z0[2]), o0 = sigf(z0[3]);
        c_reg0 = f0 * c_reg0 + i0 * g0;
        float h0v = o0 * tanhf(c_reg0);
        float i1 = sigf(z1[0]), f1 = sigf(z1[1]), g1 = tanhf(z1[2]), o1 = sigf(z1[3]);
        c_reg1 = f1 * c_reg1 + i1 * g1;
        float h1v = o1 * tanhf(c_reg1);

        // Publish h for next step + write word_emb at position tq
        g_hbuf[wb][dir][hbase + hj0][b_p] = h0v;
        g_hbuf[wb][dir][hbase + hj1][b_p] = h1v;
        size_t wo = ((size_t)b_p * TT + tq) * (2 * HH) + dir * HH + hbase;
        out[wo + hj0] = h0v;
        out[wo + hj1] = h1v;
        if (t == TT - 1) {
            size_t so = (size_t)b_p * (2 * HH) + dir * HH + hbase;
            out_sent[so + hj0] = h0v;
            out_sent[so + hj1] = h1v;
        }

        if (t < TT - 1) grid_barrier((unsigned)(t + 2));
    }
    grid_barrier_reset();
}

// ---------------------------------------------------------------------------
extern "C" void kernel_launch(void* const* d_in, const int* in_sizes, int n_in,
                              void* d_out, int out_size) {
    const float* x   = (const float*)d_in[0];
    const float* Wfk = (const float*)d_in[1];
    const float* Wfr = (const float*)d_in[2];
    const float* bf  = (const float*)d_in[3];
    const float* Wbk = (const float*)d_in[4];
    const float* Wbr = (const float*)d_in[5];
    const float* bb  = (const float*)d_in[6];
    float* out = (float*)d_out;

    size_t smem = (size_t)(512 * 32 + 512 * 64 + 32 * 64) * sizeof(float); // 200 KB
    cudaFuncSetAttribute(scan_kernel,
                         cudaFuncAttributeMaxDynamicSharedMemorySize, (int)smem);
    cudaFuncSetAttribute(proj_mma_kernel,
                         cudaFuncAttributeMaxDynamicSharedMemorySize, PROJ_SMEM);

    dim3 pg(8, 256, 2);
    proj_mma_kernel<<<pg, 512, PROJ_SMEM>>>(x, Wfk, bf, Wbk, bb);
    scan_kernel<<<NCTA, 256, smem>>>(Wfr, Wbr, out);
}